// round 3
// baseline (speedup 1.0000x reference)
#include <cuda_runtime.h>
#include <stdint.h>

// Gaussian splatting preprocess, one thread per point.
// R3: stride-3 inputs (points/scales/colors) staged via smem float4 loads
//     (kills the 3x L1-wavefront replay), regs capped for 6 blocks/SM.

__device__ __forceinline__ float scalar_to_float(const int* p) {
    int v = __ldg(p);
    if (v >= 0 && v < (1 << 23)) return (float)v;
    return __int_as_float(v);
}

__global__ __launch_bounds__(256, 6)
void gs_pre_kernel(const float* __restrict__ points,
                   const float* __restrict__ quats,
                   const float* __restrict__ scales,
                   const float* __restrict__ colors,
                   const float* __restrict__ opacity,
                   const float* __restrict__ E,
                   const float* __restrict__ I,
                   const int* __restrict__ p_fx,
                   const int* __restrict__ p_fy,
                   const int* __restrict__ p_w,
                   const int* __restrict__ p_h,
                   const int* __restrict__ p_tile,
                   float* __restrict__ out,
                   int n)
{
    __shared__ __align__(16) float sp[768];   // points for this block
    __shared__ __align__(16) float ss[768];   // scales
    __shared__ __align__(16) float sc[768];   // colors

    const int tid = threadIdx.x;
    const int i   = blockIdx.x * 256 + tid;
    const int total3 = n * 3;

    // Cooperative float4 staging of the three stride-3 arrays.
    if (tid < 192) {
        const int g4 = blockIdx.x * 192 + tid;   // float4 index
        if ((g4 + 1) * 4 <= total3) {
            reinterpret_cast<float4*>(sp)[tid] = __ldg(reinterpret_cast<const float4*>(points) + g4);
            reinterpret_cast<float4*>(ss)[tid] = __ldg(reinterpret_cast<const float4*>(scales) + g4);
            reinterpret_cast<float4*>(sc)[tid] = __ldg(reinterpret_cast<const float4*>(colors) + g4);
        } else {
#pragma unroll
            for (int e = 0; e < 4; e++) {
                const int gf = g4 * 4 + e;
                const bool ok = gf < total3;
                sp[tid*4+e] = ok ? __ldg(points + gf) : 0.0f;
                ss[tid*4+e] = ok ? __ldg(scales + gf) : 0.0f;
                sc[tid*4+e] = ok ? __ldg(colors + gf) : 0.0f;
            }
        }
    }
    __syncthreads();

    if (i >= n) return;

    // Remaining per-point loads (already vector/coalesced-friendly)
    const float4 q  = __ldg(reinterpret_cast<const float4*>(quats) + i);
    const float  op = __ldg(opacity + i);

    const float p0 = sp[3*tid + 0];
    const float p1 = sp[3*tid + 1];
    const float p2 = sp[3*tid + 2];
    const float s0 = ss[3*tid + 0];
    const float s1 = ss[3*tid + 1];
    const float s2 = ss[3*tid + 2];

    const float fx   = scalar_to_float(p_fx);
    const float fy   = scalar_to_float(p_fy);
    const float fw   = scalar_to_float(p_w);
    const float fh   = scalar_to_float(p_h);
    const float tile = scalar_to_float(p_tile);
    const float rtile = 1.0f / tile;   // tile is a power of 2 -> exact

    const float clipX = 1.3f * (fw / (2.0f * fx));
    const float clipY = 1.3f * (fh / (2.0f * fy));

    // ---- quaternion -> rotation ----
    const float qn = rsqrtf(q.x*q.x + q.y*q.y + q.z*q.z + q.w*q.w);
    const float r  = q.x * qn;
    const float qx = q.y * qn;
    const float qy = q.z * qn;
    const float qz = q.w * qn;

    const float M00 = (1.0f - 2.0f*(qy*qy + qz*qz)) * s0;
    const float M01 = (2.0f*(qx*qy - r*qz))         * s1;
    const float M02 = (2.0f*(qx*qz + r*qy))         * s2;
    const float M10 = (2.0f*(qx*qy + r*qz))         * s0;
    const float M11 = (1.0f - 2.0f*(qx*qx + qz*qz)) * s1;
    const float M12 = (2.0f*(qy*qz - r*qx))         * s2;
    const float M20 = (2.0f*(qx*qz - r*qy))         * s0;
    const float M21 = (2.0f*(qy*qz + r*qx))         * s1;
    const float M22 = (1.0f - 2.0f*(qx*qx + qy*qy)) * s2;

    const float S00 = M00*M00 + M01*M01 + M02*M02;
    const float S01 = M00*M10 + M01*M11 + M02*M12;
    const float S02 = M00*M20 + M01*M21 + M02*M22;
    const float S11 = M10*M10 + M11*M11 + M12*M12;
    const float S12 = M10*M20 + M11*M21 + M12*M22;
    const float S22 = M20*M20 + M21*M21 + M22*M22;

    // pc = [p,1] @ E
    const float pc0 = p0*__ldg(E+0) + p1*__ldg(E+4) + p2*__ldg(E+8)  + __ldg(E+12);
    const float pc1 = p0*__ldg(E+1) + p1*__ldg(E+5) + p2*__ldg(E+9)  + __ldg(E+13);
    const float pc2 = p0*__ldg(E+2) + p1*__ldg(E+6) + p2*__ldg(E+10) + __ldg(E+14);
    const float pc3 = p0*__ldg(E+3) + p1*__ldg(E+7) + p2*__ldg(E+11) + __ldg(E+15);

    const float zc    = pc2;
    const bool  zmask = (zc > 0.2f);
    const float zs    = zmask ? zc : 1.0f;
    const float rz    = 1.0f / zs;

    const float xv = fminf(fmaxf(pc0 * rz, -clipX), clipX) * zc;
    const float yv = fminf(fmaxf(pc1 * rz, -clipY), clipY) * zc;

    const float j00 = fx * rz;
    const float j11 = fy * rz;
    const float rz2 = rz * rz;
    const float j02 = -(fx * xv) * rz2;
    const float j12 = -(fy * yv) * rz2;

    const float t00 = __ldg(E+0)*j00 + __ldg(E+2)*j02;
    const float t01 = __ldg(E+4)*j00 + __ldg(E+6)*j02;
    const float t02 = __ldg(E+8)*j00 + __ldg(E+10)*j02;
    const float t10 = __ldg(E+1)*j11 + __ldg(E+2)*j12;
    const float t11 = __ldg(E+5)*j11 + __ldg(E+6)*j12;
    const float t12 = __ldg(E+9)*j11 + __ldg(E+10)*j12;

    const float u0 = S00*t00 + S01*t01 + S02*t02;
    const float u1 = S01*t00 + S11*t01 + S12*t02;
    const float u2 = S02*t00 + S12*t01 + S22*t02;
    const float v0 = S00*t10 + S01*t11 + S02*t12;
    const float v1 = S01*t10 + S11*t11 + S12*t12;
    const float v2 = S02*t10 + S12*t11 + S22*t12;

    const float a = t00*u0 + t01*u1 + t02*u2 + 0.3f;
    const float b = t10*u0 + t11*u1 + t12*u2;
    const float d = t10*v0 + t11*v1 + t12*v2 + 0.3f;

    // ndc = pc @ I
    const float n0 = pc0*__ldg(I+0) + pc1*__ldg(I+4) + pc2*__ldg(I+8)  + pc3*__ldg(I+12);
    const float n1 = pc0*__ldg(I+1) + pc1*__ldg(I+5) + pc2*__ldg(I+9)  + pc3*__ldg(I+13);
    const float n2 = pc0*__ldg(I+2) + pc1*__ldg(I+6) + pc2*__ldg(I+10) + pc3*__ldg(I+14);
    const float n3 = pc0*__ldg(I+3) + pc1*__ldg(I+7) + pc2*__ldg(I+11) + pc3*__ldg(I+15);

    const float rw = 1.0f / (zmask ? n3 : 1.0f);
    const float nx = n0 * rw;
    const float ny = n1 * rw;
    const float nz = n2;

    const bool mask = (nz > 0.2f) && (nx < 1.3f) && (nx > -1.3f)
                                  && (ny < 1.3f) && (ny > -1.3f);

    const float det  = a*d - b*b;
    const float dets = (fabsf(det) < 1e-12f) ? 1e-12f : det;
    const float idet = 1.0f / dets;

    const float mid  = 0.5f * (a + d);
    const float sv   = sqrtf(fmaxf(mid*mid - det, 0.1f));
    const float radius = ceilf(3.0f * sqrtf(fmaxf(mid + sv, 1e-6f)));

    const float px = ((nx + 1.0f) * fw - 1.0f) * 0.5f;
    const float py = ((ny + 1.0f) * fh - 1.0f) * 0.5f;

    const int max_tx = (int)ceilf(fw * rtile) - 1;
    const int max_ty = (int)ceilf(fh * rtile) - 1;

    int tlx = (int)((px - radius) * rtile);
    int tly = (int)((py - radius) * rtile);
    int brx = (int)((px + radius) * rtile);
    int bry = (int)((py + radius) * rtile);
    tlx = min(max(tlx, 0), max_tx);
    tly = min(max(tly, 0), max_ty);
    brx = min(max(brx, 0), max_tx);
    bry = min(max(bry, 0), max_ty);

    const int span  = max(brx + 1 - tlx, 1) * max(bry + 1 - tly, 1);
    const int tiles = mask ? span : 0;

    const float c0 = sc[3*tid + 0];
    const float c1 = sc[3*tid + 1];
    const float c2 = sc[3*tid + 2];

    float4 f0, f1, f2, f3;
    if (mask) {
        f0 = make_float4(px, py, nz, a);
        f1 = make_float4(b, b, d, d * idet);
        f2 = make_float4(-b * idet, -b * idet, a * idet, radius);
        f3 = make_float4(c0, c1, c2, op);
    } else {
        f0 = make_float4(0.f, 0.f, 0.f, 0.f);
        f1 = f0; f2 = f0; f3 = f0;
    }

    float4* o4 = reinterpret_cast<float4*>(out) + (size_t)i * 4;
    o4[0] = f0; o4[1] = f1; o4[2] = f2; o4[3] = f3;

    const size_t N = (size_t)n;
    out[16*N + i] = (float)tiles;
    out[17*N + i] = (float)tlx;
    out[18*N + i] = (float)tly;
    out[19*N + i] = (float)brx;
    out[20*N + i] = (float)bry;
    out[21*N + i] = mask ? 1.0f : 0.0f;
}

extern "C" void kernel_launch(void* const* d_in, const int* in_sizes, int n_in,
                              void* d_out, int out_size)
{
    const float* points  = (const float*)d_in[0];
    const float* quats   = (const float*)d_in[1];
    const float* scales  = (const float*)d_in[2];
    const float* colors  = (const float*)d_in[3];
    const float* opacity = (const float*)d_in[4];
    const float* E       = (const float*)d_in[5];
    const float* I       = (const float*)d_in[6];
    const int*   p_fx    = (const int*)d_in[7];
    const int*   p_fy    = (const int*)d_in[8];
    const int*   p_w     = (const int*)d_in[9];
    const int*   p_h     = (const int*)d_in[10];
    const int*   p_tile  = (const int*)d_in[11];

    const int n = in_sizes[0] / 3;
    float* out = (float*)d_out;

    const int threads = 256;
    const int blocks  = (n + threads - 1) / threads;
    gs_pre_kernel<<<blocks, threads>>>(points, quats, scales, colors, opacity,
                                       E, I, p_fx, p_fy, p_w, p_h, p_tile,
                                       out, n);
}

// round 4
// speedup vs baseline: 1.0994x; 1.0994x over previous
#include <cuda_runtime.h>
#include <stdint.h>

// Gaussian splatting preprocess.
// R4: R2 structure (direct scalar loads, no smem) + 2 points/thread with
//     software prefetch pipeline: loads for point k+1 issued before compute
//     of point k. launch_bounds(256,4) -> 64 regs.

__device__ __forceinline__ float scalar_to_float(const int* p) {
    int v = __ldg(p);
    if (v >= 0 && v < (1 << 23)) return (float)v;
    return __int_as_float(v);
}

struct PtIn {
    float p0, p1, p2;
    float4 q;
    float s0, s1, s2;
    float c0, c1, c2;
    float op;
};

__device__ __forceinline__ PtIn load_point(const float* __restrict__ points,
                                           const float* __restrict__ quats,
                                           const float* __restrict__ scales,
                                           const float* __restrict__ colors,
                                           const float* __restrict__ opacity,
                                           int i)
{
    PtIn v;
    v.p0 = __ldg(points + 3*i + 0);
    v.p1 = __ldg(points + 3*i + 1);
    v.p2 = __ldg(points + 3*i + 2);
    v.q  = __ldg(reinterpret_cast<const float4*>(quats) + i);
    v.s0 = __ldg(scales + 3*i + 0);
    v.s1 = __ldg(scales + 3*i + 1);
    v.s2 = __ldg(scales + 3*i + 2);
    v.c0 = __ldg(colors + 3*i + 0);
    v.c1 = __ldg(colors + 3*i + 1);
    v.c2 = __ldg(colors + 3*i + 2);
    v.op = __ldg(opacity + i);
    return v;
}

__device__ __forceinline__ void process_point(
    const PtIn& in, int i, size_t N,
    const float* __restrict__ E, const float* __restrict__ I,
    float fx, float fy, float fw, float fh, float rtile,
    float clipX, float clipY, int max_tx, int max_ty,
    float* __restrict__ out)
{
    // ---- quaternion -> rotation ----
    const float4 q = in.q;
    const float qn = rsqrtf(q.x*q.x + q.y*q.y + q.z*q.z + q.w*q.w);
    const float r  = q.x * qn;
    const float qx = q.y * qn;
    const float qy = q.z * qn;
    const float qz = q.w * qn;

    const float M00 = (1.0f - 2.0f*(qy*qy + qz*qz)) * in.s0;
    const float M01 = (2.0f*(qx*qy - r*qz))         * in.s1;
    const float M02 = (2.0f*(qx*qz + r*qy))         * in.s2;
    const float M10 = (2.0f*(qx*qy + r*qz))         * in.s0;
    const float M11 = (1.0f - 2.0f*(qx*qx + qz*qz)) * in.s1;
    const float M12 = (2.0f*(qy*qz - r*qx))         * in.s2;
    const float M20 = (2.0f*(qx*qz - r*qy))         * in.s0;
    const float M21 = (2.0f*(qy*qz + r*qx))         * in.s1;
    const float M22 = (1.0f - 2.0f*(qx*qx + qy*qy)) * in.s2;

    const float S00 = M00*M00 + M01*M01 + M02*M02;
    const float S01 = M00*M10 + M01*M11 + M02*M12;
    const float S02 = M00*M20 + M01*M21 + M02*M22;
    const float S11 = M10*M10 + M11*M11 + M12*M12;
    const float S12 = M10*M20 + M11*M21 + M12*M22;
    const float S22 = M20*M20 + M21*M21 + M22*M22;

    // pc = [p,1] @ E
    const float pc0 = in.p0*__ldg(E+0) + in.p1*__ldg(E+4) + in.p2*__ldg(E+8)  + __ldg(E+12);
    const float pc1 = in.p0*__ldg(E+1) + in.p1*__ldg(E+5) + in.p2*__ldg(E+9)  + __ldg(E+13);
    const float pc2 = in.p0*__ldg(E+2) + in.p1*__ldg(E+6) + in.p2*__ldg(E+10) + __ldg(E+14);
    const float pc3 = in.p0*__ldg(E+3) + in.p1*__ldg(E+7) + in.p2*__ldg(E+11) + __ldg(E+15);

    const float zc    = pc2;
    const bool  zmask = (zc > 0.2f);
    const float zs    = zmask ? zc : 1.0f;
    const float rz    = 1.0f / zs;

    const float xv = fminf(fmaxf(pc0 * rz, -clipX), clipX) * zc;
    const float yv = fminf(fmaxf(pc1 * rz, -clipY), clipY) * zc;

    const float j00 = fx * rz;
    const float j11 = fy * rz;
    const float rz2 = rz * rz;
    const float j02 = -(fx * xv) * rz2;
    const float j12 = -(fy * yv) * rz2;

    const float t00 = __ldg(E+0)*j00 + __ldg(E+2)*j02;
    const float t01 = __ldg(E+4)*j00 + __ldg(E+6)*j02;
    const float t02 = __ldg(E+8)*j00 + __ldg(E+10)*j02;
    const float t10 = __ldg(E+1)*j11 + __ldg(E+2)*j12;
    const float t11 = __ldg(E+5)*j11 + __ldg(E+6)*j12;
    const float t12 = __ldg(E+9)*j11 + __ldg(E+10)*j12;

    const float u0 = S00*t00 + S01*t01 + S02*t02;
    const float u1 = S01*t00 + S11*t01 + S12*t02;
    const float u2 = S02*t00 + S12*t01 + S22*t02;
    const float v0 = S00*t10 + S01*t11 + S02*t12;
    const float v1 = S01*t10 + S11*t11 + S12*t12;
    const float v2 = S02*t10 + S12*t11 + S22*t12;

    const float a = t00*u0 + t01*u1 + t02*u2 + 0.3f;
    const float b = t10*u0 + t11*u1 + t12*u2;
    const float d = t10*v0 + t11*v1 + t12*v2 + 0.3f;

    // ndc = pc @ I
    const float n0 = pc0*__ldg(I+0) + pc1*__ldg(I+4) + pc2*__ldg(I+8)  + pc3*__ldg(I+12);
    const float n1 = pc0*__ldg(I+1) + pc1*__ldg(I+5) + pc2*__ldg(I+9)  + pc3*__ldg(I+13);
    const float n2 = pc0*__ldg(I+2) + pc1*__ldg(I+6) + pc2*__ldg(I+10) + pc3*__ldg(I+14);
    const float n3 = pc0*__ldg(I+3) + pc1*__ldg(I+7) + pc2*__ldg(I+11) + pc3*__ldg(I+15);

    const float rw = 1.0f / (zmask ? n3 : 1.0f);
    const float nx = n0 * rw;
    const float ny = n1 * rw;
    const float nz = n2;

    const bool mask = (nz > 0.2f) && (nx < 1.3f) && (nx > -1.3f)
                                  && (ny < 1.3f) && (ny > -1.3f);

    const float det  = a*d - b*b;
    const float dets = (fabsf(det) < 1e-12f) ? 1e-12f : det;
    const float idet = 1.0f / dets;

    const float mid  = 0.5f * (a + d);
    const float sv   = sqrtf(fmaxf(mid*mid - det, 0.1f));
    const float radius = ceilf(3.0f * sqrtf(fmaxf(mid + sv, 1e-6f)));

    const float px = ((nx + 1.0f) * fw - 1.0f) * 0.5f;
    const float py = ((ny + 1.0f) * fh - 1.0f) * 0.5f;

    int tlx = (int)((px - radius) * rtile);
    int tly = (int)((py - radius) * rtile);
    int brx = (int)((px + radius) * rtile);
    int bry = (int)((py + radius) * rtile);
    tlx = min(max(tlx, 0), max_tx);
    tly = min(max(tly, 0), max_ty);
    brx = min(max(brx, 0), max_tx);
    bry = min(max(bry, 0), max_ty);

    const int span  = max(brx + 1 - tlx, 1) * max(bry + 1 - tly, 1);
    const int tiles = mask ? span : 0;

    float4 f0, f1, f2, f3;
    if (mask) {
        f0 = make_float4(px, py, nz, a);
        f1 = make_float4(b, b, d, d * idet);
        f2 = make_float4(-b * idet, -b * idet, a * idet, radius);
        f3 = make_float4(in.c0, in.c1, in.c2, in.op);
    } else {
        f0 = make_float4(0.f, 0.f, 0.f, 0.f);
        f1 = f0; f2 = f0; f3 = f0;
    }

    float4* o4 = reinterpret_cast<float4*>(out) + (size_t)i * 4;
    o4[0] = f0; o4[1] = f1; o4[2] = f2; o4[3] = f3;

    out[16*N + i] = (float)tiles;
    out[17*N + i] = (float)tlx;
    out[18*N + i] = (float)tly;
    out[19*N + i] = (float)brx;
    out[20*N + i] = (float)bry;
    out[21*N + i] = mask ? 1.0f : 0.0f;
}

__global__ __launch_bounds__(256, 4)
void gs_pre_kernel(const float* __restrict__ points,
                   const float* __restrict__ quats,
                   const float* __restrict__ scales,
                   const float* __restrict__ colors,
                   const float* __restrict__ opacity,
                   const float* __restrict__ E,
                   const float* __restrict__ I,
                   const int* __restrict__ p_fx,
                   const int* __restrict__ p_fy,
                   const int* __restrict__ p_w,
                   const int* __restrict__ p_h,
                   const int* __restrict__ p_tile,
                   float* __restrict__ out,
                   int n)
{
    const int stride = gridDim.x * blockDim.x;
    int i = blockIdx.x * blockDim.x + threadIdx.x;
    if (i >= n) return;

    const float fx   = scalar_to_float(p_fx);
    const float fy   = scalar_to_float(p_fy);
    const float fw   = scalar_to_float(p_w);
    const float fh   = scalar_to_float(p_h);
    const float tile = scalar_to_float(p_tile);
    const float rtile = 1.0f / tile;                 // tile = 16 -> exact
    const float clipX = 1.3f * (fw / (2.0f * fx));
    const float clipY = 1.3f * (fh / (2.0f * fy));
    const int max_tx = (int)ceilf(fw * rtile) - 1;
    const int max_ty = (int)ceilf(fh * rtile) - 1;
    const size_t N = (size_t)n;

    // --- iteration 0: issue loads for i, then immediately issue loads for
    //     i+stride (prefetch), then compute/store i. ---
    PtIn cur = load_point(points, quats, scales, colors, opacity, i);

    const int i1 = i + stride;
    const bool has1 = (i1 < n);
    // Clamped prefetch: always in-bounds; result discarded if !has1.
    PtIn nxt = load_point(points, quats, scales, colors, opacity,
                          has1 ? i1 : i);

    process_point(cur, i, N, E, I, fx, fy, fw, fh, rtile,
                  clipX, clipY, max_tx, max_ty, out);

    if (has1) {
        process_point(nxt, i1, N, E, I, fx, fy, fw, fh, rtile,
                      clipX, clipY, max_tx, max_ty, out);
    }
}

extern "C" void kernel_launch(void* const* d_in, const int* in_sizes, int n_in,
                              void* d_out, int out_size)
{
    const float* points  = (const float*)d_in[0];
    const float* quats   = (const float*)d_in[1];
    const float* scales  = (const float*)d_in[2];
    const float* colors  = (const float*)d_in[3];
    const float* opacity = (const float*)d_in[4];
    const float* E       = (const float*)d_in[5];
    const float* I       = (const float*)d_in[6];
    const int*   p_fx    = (const int*)d_in[7];
    const int*   p_fy    = (const int*)d_in[8];
    const int*   p_w     = (const int*)d_in[9];
    const int*   p_h     = (const int*)d_in[10];
    const int*   p_tile  = (const int*)d_in[11];

    const int n = in_sizes[0] / 3;
    float* out = (float*)d_out;

    const int threads = 256;
    const int blocks  = (n + threads * 2 - 1) / (threads * 2);
    gs_pre_kernel<<<blocks, threads>>>(points, quats, scales, colors, opacity,
                                       E, I, p_fx, p_fy, p_w, p_h, p_tile,
                                       out, n);
}

// round 5
// speedup vs baseline: 1.1178x; 1.0167x over previous
#include <cuda_runtime.h>
#include <stdint.h>

// Gaussian splatting preprocess.
// R5: ILP-2 prefetch pipeline restricted to the latency-critical inputs
//     (points/quats/scales); colors/opacity loaded inside process (their
//     latency hides under the covariance math). launch_bounds(128,9)=56 regs.

__device__ __forceinline__ float scalar_to_float(const int* p) {
    int v = __ldg(p);
    if (v >= 0 && v < (1 << 23)) return (float)v;
    return __int_as_float(v);
}

struct PtIn {
    float p0, p1, p2;
    float4 q;
    float s0, s1, s2;
};

__device__ __forceinline__ PtIn load_point(const float* __restrict__ points,
                                           const float* __restrict__ quats,
                                           const float* __restrict__ scales,
                                           int i)
{
    PtIn v;
    v.p0 = __ldg(points + 3*i + 0);
    v.p1 = __ldg(points + 3*i + 1);
    v.p2 = __ldg(points + 3*i + 2);
    v.q  = __ldg(reinterpret_cast<const float4*>(quats) + i);
    v.s0 = __ldg(scales + 3*i + 0);
    v.s1 = __ldg(scales + 3*i + 1);
    v.s2 = __ldg(scales + 3*i + 2);
    return v;
}

__device__ __forceinline__ void process_point(
    const PtIn& in, int i, size_t N,
    const float* __restrict__ E, const float* __restrict__ I,
    const float* __restrict__ colors, const float* __restrict__ opacity,
    float fx, float fy, float fw, float fh, float rtile,
    float clipX, float clipY, int max_tx, int max_ty,
    float* __restrict__ out)
{
    // Issue the store-time loads first; ~200+ cycles of math below hides them.
    const float c0 = __ldg(colors + 3*i + 0);
    const float c1 = __ldg(colors + 3*i + 1);
    const float c2 = __ldg(colors + 3*i + 2);
    const float op = __ldg(opacity + i);

    // ---- quaternion -> rotation ----
    const float4 q = in.q;
    const float qn = rsqrtf(q.x*q.x + q.y*q.y + q.z*q.z + q.w*q.w);
    const float r  = q.x * qn;
    const float qx = q.y * qn;
    const float qy = q.z * qn;
    const float qz = q.w * qn;

    const float M00 = (1.0f - 2.0f*(qy*qy + qz*qz)) * in.s0;
    const float M01 = (2.0f*(qx*qy - r*qz))         * in.s1;
    const float M02 = (2.0f*(qx*qz + r*qy))         * in.s2;
    const float M10 = (2.0f*(qx*qy + r*qz))         * in.s0;
    const float M11 = (1.0f - 2.0f*(qx*qx + qz*qz)) * in.s1;
    const float M12 = (2.0f*(qy*qz - r*qx))         * in.s2;
    const float M20 = (2.0f*(qx*qz - r*qy))         * in.s0;
    const float M21 = (2.0f*(qy*qz + r*qx))         * in.s1;
    const float M22 = (1.0f - 2.0f*(qx*qx + qy*qy)) * in.s2;

    const float S00 = M00*M00 + M01*M01 + M02*M02;
    const float S01 = M00*M10 + M01*M11 + M02*M12;
    const float S02 = M00*M20 + M01*M21 + M02*M22;
    const float S11 = M10*M10 + M11*M11 + M12*M12;
    const float S12 = M10*M20 + M11*M21 + M12*M22;
    const float S22 = M20*M20 + M21*M21 + M22*M22;

    // pc = [p,1] @ E
    const float pc0 = in.p0*__ldg(E+0) + in.p1*__ldg(E+4) + in.p2*__ldg(E+8)  + __ldg(E+12);
    const float pc1 = in.p0*__ldg(E+1) + in.p1*__ldg(E+5) + in.p2*__ldg(E+9)  + __ldg(E+13);
    const float pc2 = in.p0*__ldg(E+2) + in.p1*__ldg(E+6) + in.p2*__ldg(E+10) + __ldg(E+14);
    const float pc3 = in.p0*__ldg(E+3) + in.p1*__ldg(E+7) + in.p2*__ldg(E+11) + __ldg(E+15);

    const float zc    = pc2;
    const bool  zmask = (zc > 0.2f);
    const float zs    = zmask ? zc : 1.0f;
    const float rz    = 1.0f / zs;

    const float xv = fminf(fmaxf(pc0 * rz, -clipX), clipX) * zc;
    const float yv = fminf(fmaxf(pc1 * rz, -clipY), clipY) * zc;

    const float j00 = fx * rz;
    const float j11 = fy * rz;
    const float rz2 = rz * rz;
    const float j02 = -(fx * xv) * rz2;
    const float j12 = -(fy * yv) * rz2;

    const float t00 = __ldg(E+0)*j00 + __ldg(E+2)*j02;
    const float t01 = __ldg(E+4)*j00 + __ldg(E+6)*j02;
    const float t02 = __ldg(E+8)*j00 + __ldg(E+10)*j02;
    const float t10 = __ldg(E+1)*j11 + __ldg(E+2)*j12;
    const float t11 = __ldg(E+5)*j11 + __ldg(E+6)*j12;
    const float t12 = __ldg(E+9)*j11 + __ldg(E+10)*j12;

    const float u0 = S00*t00 + S01*t01 + S02*t02;
    const float u1 = S01*t00 + S11*t01 + S12*t02;
    const float u2 = S02*t00 + S12*t01 + S22*t02;
    const float v0 = S00*t10 + S01*t11 + S02*t12;
    const float v1 = S01*t10 + S11*t11 + S12*t12;
    const float v2 = S02*t10 + S12*t11 + S22*t12;

    const float a = t00*u0 + t01*u1 + t02*u2 + 0.3f;
    const float b = t10*u0 + t11*u1 + t12*u2;
    const float d = t10*v0 + t11*v1 + t12*v2 + 0.3f;

    // ndc = pc @ I
    const float n0 = pc0*__ldg(I+0) + pc1*__ldg(I+4) + pc2*__ldg(I+8)  + pc3*__ldg(I+12);
    const float n1 = pc0*__ldg(I+1) + pc1*__ldg(I+5) + pc2*__ldg(I+9)  + pc3*__ldg(I+13);
    const float n2 = pc0*__ldg(I+2) + pc1*__ldg(I+6) + pc2*__ldg(I+10) + pc3*__ldg(I+14);
    const float n3 = pc0*__ldg(I+3) + pc1*__ldg(I+7) + pc2*__ldg(I+11) + pc3*__ldg(I+15);

    const float rw = 1.0f / (zmask ? n3 : 1.0f);
    const float nx = n0 * rw;
    const float ny = n1 * rw;
    const float nz = n2;

    const bool mask = (nz > 0.2f) && (nx < 1.3f) && (nx > -1.3f)
                                  && (ny < 1.3f) && (ny > -1.3f);

    const float det  = a*d - b*b;
    const float dets = (fabsf(det) < 1e-12f) ? 1e-12f : det;
    const float idet = 1.0f / dets;

    const float mid  = 0.5f * (a + d);
    const float sv   = sqrtf(fmaxf(mid*mid - det, 0.1f));
    const float radius = ceilf(3.0f * sqrtf(fmaxf(mid + sv, 1e-6f)));

    const float px = ((nx + 1.0f) * fw - 1.0f) * 0.5f;
    const float py = ((ny + 1.0f) * fh - 1.0f) * 0.5f;

    int tlx = (int)((px - radius) * rtile);
    int tly = (int)((py - radius) * rtile);
    int brx = (int)((px + radius) * rtile);
    int bry = (int)((py + radius) * rtile);
    tlx = min(max(tlx, 0), max_tx);
    tly = min(max(tly, 0), max_ty);
    brx = min(max(brx, 0), max_tx);
    bry = min(max(bry, 0), max_ty);

    const int span  = max(brx + 1 - tlx, 1) * max(bry + 1 - tly, 1);
    const int tiles = mask ? span : 0;

    float4 f0, f1, f2, f3;
    if (mask) {
        f0 = make_float4(px, py, nz, a);
        f1 = make_float4(b, b, d, d * idet);
        f2 = make_float4(-b * idet, -b * idet, a * idet, radius);
        f3 = make_float4(c0, c1, c2, op);
    } else {
        f0 = make_float4(0.f, 0.f, 0.f, 0.f);
        f1 = f0; f2 = f0; f3 = f0;
    }

    float4* o4 = reinterpret_cast<float4*>(out) + (size_t)i * 4;
    o4[0] = f0; o4[1] = f1; o4[2] = f2; o4[3] = f3;

    out[16*N + i] = (float)tiles;
    out[17*N + i] = (float)tlx;
    out[18*N + i] = (float)tly;
    out[19*N + i] = (float)brx;
    out[20*N + i] = (float)bry;
    out[21*N + i] = mask ? 1.0f : 0.0f;
}

__global__ __launch_bounds__(128, 9)
void gs_pre_kernel(const float* __restrict__ points,
                   const float* __restrict__ quats,
                   const float* __restrict__ scales,
                   const float* __restrict__ colors,
                   const float* __restrict__ opacity,
                   const float* __restrict__ E,
                   const float* __restrict__ I,
                   const int* __restrict__ p_fx,
                   const int* __restrict__ p_fy,
                   const int* __restrict__ p_w,
                   const int* __restrict__ p_h,
                   const int* __restrict__ p_tile,
                   float* __restrict__ out,
                   int n)
{
    const int stride = gridDim.x * blockDim.x;
    int i = blockIdx.x * blockDim.x + threadIdx.x;
    if (i >= n) return;

    const float fx   = scalar_to_float(p_fx);
    const float fy   = scalar_to_float(p_fy);
    const float fw   = scalar_to_float(p_w);
    const float fh   = scalar_to_float(p_h);
    const float tile = scalar_to_float(p_tile);
    const float rtile = 1.0f / tile;                 // tile = 16 -> exact
    const float clipX = 1.3f * (fw / (2.0f * fx));
    const float clipY = 1.3f * (fh / (2.0f * fy));
    const int max_tx = (int)ceilf(fw * rtile) - 1;
    const int max_ty = (int)ceilf(fh * rtile) - 1;
    const size_t N = (size_t)n;

    PtIn cur = load_point(points, quats, scales, i);

    const int i1 = i + stride;
    const bool has1 = (i1 < n);
    PtIn nxt = load_point(points, quats, scales, has1 ? i1 : i);

    process_point(cur, i, N, E, I, colors, opacity,
                  fx, fy, fw, fh, rtile, clipX, clipY, max_tx, max_ty, out);

    if (has1) {
        process_point(nxt, i1, N, E, I, colors, opacity,
                      fx, fy, fw, fh, rtile, clipX, clipY, max_tx, max_ty, out);
    }
}

extern "C" void kernel_launch(void* const* d_in, const int* in_sizes, int n_in,
                              void* d_out, int out_size)
{
    const float* points  = (const float*)d_in[0];
    const float* quats   = (const float*)d_in[1];
    const float* scales  = (const float*)d_in[2];
    const float* colors  = (const float*)d_in[3];
    const float* opacity = (const float*)d_in[4];
    const float* E       = (const float*)d_in[5];
    const float* I       = (const float*)d_in[6];
    const int*   p_fx    = (const int*)d_in[7];
    const int*   p_fy    = (const int*)d_in[8];
    const int*   p_w     = (const int*)d_in[9];
    const int*   p_h     = (const int*)d_in[10];
    const int*   p_tile  = (const int*)d_in[11];

    const int n = in_sizes[0] / 3;
    float* out = (float*)d_out;

    const int threads = 128;
    const int blocks  = (n + threads * 2 - 1) / (threads * 2);
    gs_pre_kernel<<<blocks, threads>>>(points, quats, scales, colors, opacity,
                                       E, I, p_fx, p_fy, p_w, p_h, p_tile,
                                       out, n);
}